// round 8
// baseline (speedup 1.0000x reference)
#include <cuda_runtime.h>
#include <cuda_bf16.h>
#include <cstdint>
#include <cstddef>

// ---------------- problem constants ----------------
constexpr int LQ    = 13294;
constexpr int MROWS = 2 * LQ;          // 26588
constexpr int MPAD  = 208 * 128;       // 26624

__constant__ int c_WH[4] = {100, 50, 25, 13};
__constant__ int c_ST[4] = {0, 10000, 12500, 13125};

// ---------------- scratch (device globals) ----------------
__device__ float g_value[MPAD * 256];
__device__ float g_qc   [MPAD * 384];             // [off(256) | logits(128)] per row
__device__ float g_samp [MPAD * 256];
__device__ float g_bqc  [384];                    // boff ++ battn
__device__ __nv_bfloat16 g_wthi[896 * 256];
__device__ __nv_bfloat16 g_wtlo[896 * 256];

// ---------------- PTX helpers (baseline sm_80+ ISA, legal on compute_103) ----
__device__ __forceinline__ uint32_t smem_u32(const void* p) {
    uint32_t a;
    asm("{ .reg .u64 t; cvta.to.shared.u64 t, %1; cvt.u32.u64 %0, t; }" : "=r"(a) : "l"(p));
    return a;
}
__device__ __forceinline__ void ldsm_x4(uint32_t addr, uint32_t* r) {
    asm volatile("ldmatrix.sync.aligned.m8n8.x4.shared.b16 {%0,%1,%2,%3}, [%4];"
                 : "=r"(r[0]), "=r"(r[1]), "=r"(r[2]), "=r"(r[3]) : "r"(addr));
}
__device__ __forceinline__ void mma_bf16(float* c, const uint32_t* a, const uint32_t* b) {
    asm volatile("mma.sync.aligned.m16n8k16.row.col.f32.bf16.bf16.f32 "
                 "{%0,%1,%2,%3}, {%4,%5,%6,%7}, {%8,%9}, {%0,%1,%2,%3};"
                 : "+f"(c[0]), "+f"(c[1]), "+f"(c[2]), "+f"(c[3])
                 : "r"(a[0]), "r"(a[1]), "r"(a[2]), "r"(a[3]), "r"(b[0]), "r"(b[1]));
}
#define CP_ASYNC16(dst, src) \
    asm volatile("cp.async.cg.shared.global [%0], [%1], 16;" :: "r"(dst), "l"(src) : "memory")
#define CP_COMMIT() asm volatile("cp.async.commit_group;" ::: "memory")
#define CP_WAIT1()  asm volatile("cp.async.wait_group 1;" ::: "memory")

// ---------------- weight conversion (one launch) ----------------
__global__ __launch_bounds__(256) void conv_wt_all(
    const float* __restrict__ Wv,   const float* __restrict__ Woff,
    const float* __restrict__ Wattn,const float* __restrict__ Wout,
    const float* __restrict__ boff, const float* __restrict__ battn,
    __nv_bfloat16* __restrict__ hi, __nv_bfloat16* __restrict__ lo,
    float* __restrict__ bqc)
{
    int idx = blockIdx.x * 256 + threadIdx.x;     // 896*256 total
    int ng = idx >> 8, k = idx & 255;
    float a;
    if (ng < 256)       a = Wv  [k * 256 + ng];
    else if (ng < 640) {
        int n = ng - 256;
        a = (n < 256) ? Woff[k * 256 + n] : Wattn[k * 128 + (n - 256)];
    } else              a = Wout[k * 256 + (ng - 640)];
    __nv_bfloat16 h = __float2bfloat16(a);
    hi[idx] = h;
    lo[idx] = __float2bfloat16(a - __bfloat162float(h));
    if (idx < 384) bqc[idx] = (idx < 256) ? boff[idx] : battn[idx - 256];
}

// ---------------- fused-convert HMMA GEMM core (R7, unchanged) ----------------
constexpr int ASTG  = 20480;
constexpr int OF_AH = 0, OF_AL = 10240;
constexpr int BSTG  = 20480;
constexpr int OF_BH = 0, OF_BL = 10240;
constexpr int BBASE = 2 * ASTG;
constexpr int GSMEM = BBASE + 3 * BSTG;            // 102400 -> 2 CTAs/SM

__device__ __forceinline__ void gemm_core(
    const float* __restrict__ A,
    const __nv_bfloat16* __restrict__ Bhi, const __nv_bfloat16* __restrict__ Blo,
    const float* __restrict__ bias, float* __restrict__ C,
    int M, int ldc, int m0, int n0, char* smem)
{
    const uint32_t sm0 = smem_u32(smem);
    const int tid = threadIdx.x, wid = tid >> 5, lane = tid & 31;
    const int wm = (wid & 3) * 32, wn = (wid >> 2) * 64;

    const int arow = tid >> 1, ak0 = (tid & 1) * 16;
    const bool avalid = (m0 + arow) < M;
    const float* aptr = A + (size_t)(m0 + arow) * 256 + ak0;

    const int br = tid >> 1, bc2 = (tid & 1) * 2;

    const uint32_t aRow = (lane & 15), aColB = (uint32_t)(lane >> 4) * 16;
    const uint32_t bRow = ((uint32_t)(lane >> 4) << 3) + (lane & 7);
    const uint32_t bColB = (uint32_t)((lane >> 3) & 1) * 16;

    float acc[2][8][4] = {};
    float fA[16];

    auto ldgA = [&](int ch) {
        if (avalid) {
            const float* p = aptr + ch * 32;
            #pragma unroll
            for (int j = 0; j < 4; ++j)
                *(float4*)&fA[j * 4] = *(const float4*)(p + j * 4);
        } else {
            #pragma unroll
            for (int j = 0; j < 16; ++j) fA[j] = 0.f;
        }
    };
    auto cvtStoreA = [&](uint32_t off) {
        __nv_bfloat16 h[16], l[16];
        #pragma unroll
        for (int j = 0; j < 16; ++j) {
            h[j] = __float2bfloat16(fA[j]);
            l[j] = __float2bfloat16(fA[j] - __bfloat162float(h[j]));
        }
        const uint32_t o = arow * 80 + ak0 * 2;
        *(uint4*)(smem + off + OF_AH + o)      = ((uint4*)h)[0];
        *(uint4*)(smem + off + OF_AH + o + 16) = ((uint4*)h)[1];
        *(uint4*)(smem + off + OF_AL + o)      = ((uint4*)l)[0];
        *(uint4*)(smem + off + OF_AL + o + 16) = ((uint4*)l)[1];
    };
    auto ldB = [&](int ch) {
        const uint32_t sb = sm0 + BBASE + (ch % 3) * BSTG;
        const int k0 = ch * 32;
        #pragma unroll
        for (int i = 0; i < 2; ++i) {
            const int c = bc2 + i;
            const uint32_t dst = sb + br * 80 + c * 16;
            CP_ASYNC16(dst + OF_BH, Bhi + (size_t)(n0 + br) * 256 + k0 + c * 8);
            CP_ASYNC16(dst + OF_BL, Blo + (size_t)(n0 + br) * 256 + k0 + c * 8);
        }
        CP_COMMIT();
    };

    ldB(0); ldB(1);
    ldgA(0);
    cvtStoreA(0);

    for (int ch = 0; ch < 8; ++ch) {
        CP_WAIT1();
        __syncthreads();
        if (ch < 6) ldB(ch + 2); else CP_COMMIT();
        if (ch < 7) ldgA(ch + 1);

        const uint32_t sa = sm0 + (ch & 1) * ASTG;
        const uint32_t sb = sm0 + BBASE + (ch % 3) * BSTG;
        #pragma unroll
        for (int ks = 0; ks < 2; ++ks) {
            const uint32_t kB = ks * 32;
            uint32_t afh[2][4], afl[2][4], bf[4][4];
            #pragma unroll
            for (int mt = 0; mt < 2; ++mt) {
                const uint32_t ao = (wm + mt * 16 + aRow) * 80 + kB + aColB;
                ldsm_x4(sa + OF_AH + ao, afh[mt]);
                ldsm_x4(sa + OF_AL + ao, afl[mt]);
            }
            #pragma unroll
            for (int p = 0; p < 4; ++p)
                ldsm_x4(sb + OF_BH + (wn + p * 16 + bRow) * 80 + kB + bColB, bf[p]);
            #pragma unroll
            for (int mt = 0; mt < 2; ++mt)
                #pragma unroll
                for (int nt = 0; nt < 8; ++nt) {
                    mma_bf16(acc[mt][nt], afh[mt], &bf[nt >> 1][(nt & 1) * 2]);
                    mma_bf16(acc[mt][nt], afl[mt], &bf[nt >> 1][(nt & 1) * 2]);
                }
            #pragma unroll
            for (int p = 0; p < 4; ++p)
                ldsm_x4(sb + OF_BL + (wn + p * 16 + bRow) * 80 + kB + bColB, bf[p]);
            #pragma unroll
            for (int mt = 0; mt < 2; ++mt)
                #pragma unroll
                for (int nt = 0; nt < 8; ++nt)
                    mma_bf16(acc[mt][nt], afh[mt], &bf[nt >> 1][(nt & 1) * 2]);
        }

        if (ch < 7) cvtStoreA(((ch + 1) & 1) * ASTG);
    }

    const int g = lane >> 2, t2 = (lane & 3) * 2;
    #pragma unroll
    for (int mt = 0; mt < 2; ++mt) {
        const int r0 = m0 + wm + mt * 16 + g;
        #pragma unroll
        for (int nt = 0; nt < 8; ++nt) {
            const int c = n0 + wn + nt * 8 + t2;
            const float2 bsv = *(const float2*)(bias + c);
            if (r0 < M) {
                float2 o = { acc[mt][nt][0] + bsv.x, acc[mt][nt][1] + bsv.y };
                *(float2*)(C + (size_t)r0 * ldc + c) = o;
            }
            if (r0 + 8 < M) {
                float2 o = { acc[mt][nt][2] + bsv.x, acc[mt][nt][3] + bsv.y };
                *(float2*)(C + (size_t)(r0 + 8) * ldc + c) = o;
            }
        }
    }
}

// merged value+qc GEMM: grid.y in [0,5): y<2 -> value (N=256), y>=2 -> qc (N=384)
__global__ __launch_bounds__(256, 2) void gemm_dual(
    const float* __restrict__ A0, const __nv_bfloat16* __restrict__ B0h,
    const __nv_bfloat16* __restrict__ B0l, const float* __restrict__ bias0,
    float* __restrict__ C0,
    const float* __restrict__ A1, const __nv_bfloat16* __restrict__ B1h,
    const __nv_bfloat16* __restrict__ B1l, const float* __restrict__ bias1,
    float* __restrict__ C1, int xt0)
{
    extern __shared__ __align__(16) char smem[];
    const int m0 = (xt0 + blockIdx.x) * 128;
    if (blockIdx.y < 2)
        gemm_core(A0, B0h, B0l, bias0, C0, MROWS, 256, m0, blockIdx.y * 128, smem);
    else
        gemm_core(A1, B1h, B1l, bias1, C1, MROWS, 384, m0, (blockIdx.y - 2) * 128, smem);
}

__global__ __launch_bounds__(256, 2) void gemm_single(
    const float* __restrict__ A, const __nv_bfloat16* __restrict__ Bhi,
    const __nv_bfloat16* __restrict__ Blo, const float* __restrict__ bias,
    float* __restrict__ C, int M, int ldc, int xt0)
{
    extern __shared__ __align__(16) char smem[];
    gemm_core(A, Bhi, Blo, bias, C, M, ldc, (xt0 + blockIdx.x) * 128,
              blockIdx.y * 128, smem);
}

// ---------------- deformable sampling: precomputed corner table ----------------
__global__ __launch_bounds__(256) void sample_kernel(
    const float* __restrict__ refpts,   // [N*Lq, 4, 2]
    const float* __restrict__ value,    // [N*S, 256]
    const float* __restrict__ qc,       // [N*Lq, 384]: off(256) | logits(128)
    float* __restrict__ out,            // [N*Lq, 256]
    int qbase)
{
    const int q0  = qbase + blockIdx.x * 4;
    const int tid = threadIdx.x;

    __shared__ float sh_w[4][8][17];
    __shared__ float sh_x[4][8][17];
    __shared__ float sh_y[4][8][17];
    __shared__ __align__(16) float2 sh_p[4][8][64];

    #pragma unroll
    for (int i = 0; i < 2; ++i) {
        int run = i * 16 + (tid >> 4);
        int q = run >> 3, h = run & 7, l16 = tid & 15;
        float v = qc[(size_t)(q0 + q) * 384 + 256 + h * 16 + l16];
        float mx = v;
        #pragma unroll
        for (int o = 8; o > 0; o >>= 1) mx = fmaxf(mx, __shfl_xor_sync(0xffffffffu, mx, o));
        float e = __expf(v - mx);
        float s = e;
        #pragma unroll
        for (int o = 8; o > 0; o >>= 1) s += __shfl_xor_sync(0xffffffffu, s, o);
        sh_w[q][h][l16] = e / s;
    }

    #pragma unroll
    for (int q = 0; q < 4; ++q) {
        int h = tid >> 5, l32 = tid & 31;
        int lvl = l32 >> 3, cc = l32 & 1, s = l32 >> 1;
        float off = qc[(size_t)(q0 + q) * 384 + tid];
        float ref = refpts[((size_t)(q0 + q) * 4 + lvl) * 2 + cc];
        float pix = fmaf(ref, (float)c_WH[lvl], off) - 0.5f;
        if (cc == 0) sh_x[q][h][s] = pix; else sh_y[q][h][s] = pix;
    }
    __syncthreads();

    #pragma unroll
    for (int i = 0; i < 8; ++i) {
        const int e = i * 256 + tid;
        const int q = e >> 9, h = (e >> 6) & 7, s = (e >> 2) & 15, c = e & 3;
        const int lvl = s >> 2;
        const int Wl = c_WH[lvl], st = c_ST[lvl];
        const float x = sh_x[q][h][s], y = sh_y[q][h][s], aw = sh_w[q][h][s];
        const float xf = floorf(x), yf = floorf(y);
        const float wx = x - xf, wy = y - yf;
        const int xi = (int)xf + (c & 1);
        const int yi = (int)yf + (c >> 1);
        const float gw = aw * ((c >> 1) ? wy : 1.f - wy) * ((c & 1) ? wx : 1.f - wx);
        const bool valid = (xi >= 0) & (xi < Wl) & (yi >= 0) & (yi < Wl);
        float2 pr;
        pr.x = valid ? gw : 0.f;
        pr.y = __int_as_float(valid ? (st + yi * Wl + xi) * 1024 : 0);
        sh_p[q][h][s * 4 + c] = pr;
    }
    __syncthreads();

    const int w = tid >> 5, lane = tid & 31;
    const int q = w >> 1, half = w & 1;
    const int head = half * 4 + (lane >> 3);
    const int ci = lane & 7;
    const int qg = q0 + q;
    const int n  = (qg >= LQ) ? 1 : 0;

    const char* vb = (const char*)value + ((size_t)n * LQ * 64 + head * 8 + ci) * 16;
    const float4* pp = (const float4*)&sh_p[q][head][0];
    float4 acc = make_float4(0.f, 0.f, 0.f, 0.f);

    #pragma unroll 8
    for (int i = 0; i < 32; ++i) {
        const float4 pw = pp[i];
        const float4 v0 = __ldg((const float4*)(vb + (uint32_t)__float_as_int(pw.y)));
        const float4 v1 = __ldg((const float4*)(vb + (uint32_t)__float_as_int(pw.w)));
        acc.x = fmaf(pw.x, v0.x, acc.x);
        acc.y = fmaf(pw.x, v0.y, acc.y);
        acc.z = fmaf(pw.x, v0.z, acc.z);
        acc.w = fmaf(pw.x, v0.w, acc.w);
        acc.x = fmaf(pw.z, v1.x, acc.x);
        acc.y = fmaf(pw.z, v1.y, acc.y);
        acc.z = fmaf(pw.z, v1.z, acc.z);
        acc.w = fmaf(pw.z, v1.w, acc.w);
    }
    ((float4*)out)[(size_t)qg * 64 + head * 8 + ci] = acc;
}

// ---------------- launch: two-stream half-batch pipeline ----------------
extern "C" void kernel_launch(void* const* d_in, const int* in_sizes, int n_in,
                              void* d_out, int out_size)
{
    const float* query  = (const float*)d_in[0];
    const float* refpts = (const float*)d_in[1];
    const float* flat   = (const float*)d_in[2];
    const float* Wv     = (const float*)d_in[5];
    const float* bv     = (const float*)d_in[6];
    const float* Woff   = (const float*)d_in[7];
    const float* boff   = (const float*)d_in[8];
    const float* Wattn  = (const float*)d_in[9];
    const float* battn  = (const float*)d_in[10];
    const float* Wout   = (const float*)d_in[11];
    const float* bout   = (const float*)d_in[12];
    float* out = (float*)d_out;

    float *gv, *gqc, *gs, *gbqc;
    __nv_bfloat16 *whi, *wlo;
    cudaGetSymbolAddress((void**)&gv,   g_value);
    cudaGetSymbolAddress((void**)&gqc,  g_qc);
    cudaGetSymbolAddress((void**)&gs,   g_samp);
    cudaGetSymbolAddress((void**)&gbqc, g_bqc);
    cudaGetSymbolAddress((void**)&whi,  g_wthi);
    cudaGetSymbolAddress((void**)&wlo,  g_wtlo);

    static bool init_done = false;
    static cudaStream_t s1;
    static cudaEvent_t evA, evB, evSA, evSB;
    if (!init_done) {
        cudaFuncSetAttribute(gemm_dual,   cudaFuncAttributeMaxDynamicSharedMemorySize, GSMEM);
        cudaFuncSetAttribute(gemm_single, cudaFuncAttributeMaxDynamicSharedMemorySize, GSMEM);
        cudaStreamCreateWithFlags(&s1, cudaStreamNonBlocking);
        cudaEventCreateWithFlags(&evA,  cudaEventDisableTiming);
        cudaEventCreateWithFlags(&evB,  cudaEventDisableTiming);
        cudaEventCreateWithFlags(&evSA, cudaEventDisableTiming);
        cudaEventCreateWithFlags(&evSB, cudaEventDisableTiming);
        init_done = true;
    }

    __nv_bfloat16 *wv_h = whi + 0,          *wv_l = wlo + 0;
    __nv_bfloat16 *wq_h = whi + 256 * 256,  *wq_l = wlo + 256 * 256;
    __nv_bfloat16 *wu_h = whi + 640 * 256,  *wu_l = wlo + 640 * 256;

    // s0 (NULL stream): conv -> dualA -> dualB
    conv_wt_all<<<896, 256>>>(Wv, Woff, Wattn, Wout, boff, battn, whi, wlo, gbqc);

    // half A: tiles [0,104) = rows [0,13312); half B: tiles [104,208)
    gemm_dual<<<dim3(104, 5), 256, GSMEM>>>(flat, wv_h, wv_l, bv, gv,
                                            query, wq_h, wq_l, gbqc, gqc, 0);
    cudaEventRecord(evA, 0);
    gemm_dual<<<dim3(104, 5), 256, GSMEM>>>(flat, wv_h, wv_l, bv, gv,
                                            query, wq_h, wq_l, gbqc, gqc, 104);
    cudaEventRecord(evB, 0);

    // s1: sampleA (q in [0,13292)) overlaps dualB; sampleB (q in [13292,26588))
    cudaStreamWaitEvent(s1, evA, 0);
    sample_kernel<<<3323, 256, 0, s1>>>(refpts, gv, gqc, gs, 0);
    cudaEventRecord(evSA, s1);
    cudaStreamWaitEvent(s1, evB, 0);
    sample_kernel<<<3324, 256, 0, s1>>>(refpts, gv, gqc, gs, 13292);
    cudaEventRecord(evSB, s1);

    // s0: singleA (tiles [0,103) = rows < 13184, ready after sampleA) overlaps sampleB
    cudaStreamWaitEvent(0, evSA, 0);
    gemm_single<<<dim3(103, 2), 256, GSMEM>>>(gs, wu_h, wu_l, bout, out, MROWS, 256, 0);
    cudaStreamWaitEvent(0, evSB, 0);
    gemm_single<<<dim3(105, 2), 256, GSMEM>>>(gs, wu_h, wu_l, bout, out, MROWS, 256, 103);
}

// round 9
// speedup vs baseline: 1.2502x; 1.2502x over previous
#include <cuda_runtime.h>
#include <cuda_bf16.h>
#include <cuda_fp16.h>
#include <cstdint>
#include <cstddef>

// ---------------- problem constants ----------------
constexpr int LQ    = 13294;
constexpr int MROWS = 2 * LQ;          // 26588
constexpr int MPAD  = 208 * 128;       // 26624

__constant__ int c_WH[4] = {100, 50, 25, 13};
__constant__ int c_ST[4] = {0, 10000, 12500, 13125};

// ---------------- scratch (device globals) ----------------
__device__ __half g_value[MPAD * 256];            // fp16 value tensor
__device__ float  g_qc   [MPAD * 384];            // [off(256) | logits(128)] per row
__device__ float  g_samp [MPAD * 256];
__device__ float  g_bqc  [384];                   // boff ++ battn
__device__ __nv_bfloat16 g_wthi[896 * 256];
__device__ __nv_bfloat16 g_wtlo[896 * 256];

// ---------------- PTX helpers (baseline sm_80+ ISA, legal on compute_103) ----
__device__ __forceinline__ uint32_t smem_u32(const void* p) {
    uint32_t a;
    asm("{ .reg .u64 t; cvta.to.shared.u64 t, %1; cvt.u32.u64 %0, t; }" : "=r"(a) : "l"(p));
    return a;
}
__device__ __forceinline__ void ldsm_x4(uint32_t addr, uint32_t* r) {
    asm volatile("ldmatrix.sync.aligned.m8n8.x4.shared.b16 {%0,%1,%2,%3}, [%4];"
                 : "=r"(r[0]), "=r"(r[1]), "=r"(r[2]), "=r"(r[3]) : "r"(addr));
}
__device__ __forceinline__ void mma_bf16(float* c, const uint32_t* a, const uint32_t* b) {
    asm volatile("mma.sync.aligned.m16n8k16.row.col.f32.bf16.bf16.f32 "
                 "{%0,%1,%2,%3}, {%4,%5,%6,%7}, {%8,%9}, {%0,%1,%2,%3};"
                 : "+f"(c[0]), "+f"(c[1]), "+f"(c[2]), "+f"(c[3])
                 : "r"(a[0]), "r"(a[1]), "r"(a[2]), "r"(a[3]), "r"(b[0]), "r"(b[1]));
}
#define CP_ASYNC16(dst, src) \
    asm volatile("cp.async.cg.shared.global [%0], [%1], 16;" :: "r"(dst), "l"(src) : "memory")
#define CP_COMMIT() asm volatile("cp.async.commit_group;" ::: "memory")
#define CP_WAIT1()  asm volatile("cp.async.wait_group 1;" ::: "memory")

// ---------------- weight conversion (one launch) ----------------
__global__ __launch_bounds__(256) void conv_wt_all(
    const float* __restrict__ Wv,   const float* __restrict__ Woff,
    const float* __restrict__ Wattn,const float* __restrict__ Wout,
    const float* __restrict__ boff, const float* __restrict__ battn,
    __nv_bfloat16* __restrict__ hi, __nv_bfloat16* __restrict__ lo,
    float* __restrict__ bqc)
{
    int idx = blockIdx.x * 256 + threadIdx.x;     // 896*256 total
    int ng = idx >> 8, k = idx & 255;
    float a;
    if (ng < 256)       a = Wv  [k * 256 + ng];
    else if (ng < 640) {
        int n = ng - 256;
        a = (n < 256) ? Woff[k * 256 + n] : Wattn[k * 128 + (n - 256)];
    } else              a = Wout[k * 256 + (ng - 640)];
    __nv_bfloat16 h = __float2bfloat16(a);
    hi[idx] = h;
    lo[idx] = __float2bfloat16(a - __bfloat162float(h));
    if (idx < 384) bqc[idx] = (idx < 256) ? boff[idx] : battn[idx - 256];
}

// ---------------- fused-convert HMMA GEMM core ----------------
// C[M,N] = A_fp32[M,256] @ Wt^T + bias, split: Ahi*Bhi + Ahi*Blo + Alo*Bhi.
// Tile 128x128, BK=32, 256 threads (8 warps, warp tile 32x64).
// HalfOut: epilogue stores __half2 (value tensor) instead of float2.
constexpr int ASTG  = 20480;
constexpr int OF_AH = 0, OF_AL = 10240;
constexpr int BSTG  = 20480;
constexpr int OF_BH = 0, OF_BL = 10240;
constexpr int BBASE = 2 * ASTG;
constexpr int GSMEM = BBASE + 3 * BSTG;            // 102400 -> 2 CTAs/SM

template <bool HalfOut>
__device__ __forceinline__ void gemm_core(
    const float* __restrict__ A,
    const __nv_bfloat16* __restrict__ Bhi, const __nv_bfloat16* __restrict__ Blo,
    const float* __restrict__ bias, void* __restrict__ Cv,
    int M, int ldc, int m0, int n0, char* smem)
{
    const uint32_t sm0 = smem_u32(smem);
    const int tid = threadIdx.x, wid = tid >> 5, lane = tid & 31;
    const int wm = (wid & 3) * 32, wn = (wid >> 2) * 64;

    const int arow = tid >> 1, ak0 = (tid & 1) * 16;
    const bool avalid = (m0 + arow) < M;
    const float* aptr = A + (size_t)(m0 + arow) * 256 + ak0;

    const int br = tid >> 1, bc2 = (tid & 1) * 2;

    const uint32_t aRow = (lane & 15), aColB = (uint32_t)(lane >> 4) * 16;
    const uint32_t bRow = ((uint32_t)(lane >> 4) << 3) + (lane & 7);
    const uint32_t bColB = (uint32_t)((lane >> 3) & 1) * 16;

    float acc[2][8][4] = {};
    float fA[16];

    auto ldgA = [&](int ch) {
        if (avalid) {
            const float* p = aptr + ch * 32;
            #pragma unroll
            for (int j = 0; j < 4; ++j)
                *(float4*)&fA[j * 4] = *(const float4*)(p + j * 4);
        } else {
            #pragma unroll
            for (int j = 0; j < 16; ++j) fA[j] = 0.f;
        }
    };
    auto cvtStoreA = [&](uint32_t off) {
        __nv_bfloat16 h[16], l[16];
        #pragma unroll
        for (int j = 0; j < 16; ++j) {
            h[j] = __float2bfloat16(fA[j]);
            l[j] = __float2bfloat16(fA[j] - __bfloat162float(h[j]));
        }
        const uint32_t o = arow * 80 + ak0 * 2;
        *(uint4*)(smem + off + OF_AH + o)      = ((uint4*)h)[0];
        *(uint4*)(smem + off + OF_AH + o + 16) = ((uint4*)h)[1];
        *(uint4*)(smem + off + OF_AL + o)      = ((uint4*)l)[0];
        *(uint4*)(smem + off + OF_AL + o + 16) = ((uint4*)l)[1];
    };
    auto ldB = [&](int ch) {
        const uint32_t sb = sm0 + BBASE + (ch % 3) * BSTG;
        const int k0 = ch * 32;
        #pragma unroll
        for (int i = 0; i < 2; ++i) {
            const int c = bc2 + i;
            const uint32_t dst = sb + br * 80 + c * 16;
            CP_ASYNC16(dst + OF_BH, Bhi + (size_t)(n0 + br) * 256 + k0 + c * 8);
            CP_ASYNC16(dst + OF_BL, Blo + (size_t)(n0 + br) * 256 + k0 + c * 8);
        }
        CP_COMMIT();
    };

    ldB(0); ldB(1);
    ldgA(0);
    cvtStoreA(0);

    for (int ch = 0; ch < 8; ++ch) {
        CP_WAIT1();
        __syncthreads();
        if (ch < 6) ldB(ch + 2); else CP_COMMIT();
        if (ch < 7) ldgA(ch + 1);

        const uint32_t sa = sm0 + (ch & 1) * ASTG;
        const uint32_t sb = sm0 + BBASE + (ch % 3) * BSTG;
        #pragma unroll
        for (int ks = 0; ks < 2; ++ks) {
            const uint32_t kB = ks * 32;
            uint32_t afh[2][4], afl[2][4], bf[4][4];
            #pragma unroll
            for (int mt = 0; mt < 2; ++mt) {
                const uint32_t ao = (wm + mt * 16 + aRow) * 80 + kB + aColB;
                ldsm_x4(sa + OF_AH + ao, afh[mt]);
                ldsm_x4(sa + OF_AL + ao, afl[mt]);
            }
            #pragma unroll
            for (int p = 0; p < 4; ++p)
                ldsm_x4(sb + OF_BH + (wn + p * 16 + bRow) * 80 + kB + bColB, bf[p]);
            #pragma unroll
            for (int mt = 0; mt < 2; ++mt)
                #pragma unroll
                for (int nt = 0; nt < 8; ++nt) {
                    mma_bf16(acc[mt][nt], afh[mt], &bf[nt >> 1][(nt & 1) * 2]);
                    mma_bf16(acc[mt][nt], afl[mt], &bf[nt >> 1][(nt & 1) * 2]);
                }
            #pragma unroll
            for (int p = 0; p < 4; ++p)
                ldsm_x4(sb + OF_BL + (wn + p * 16 + bRow) * 80 + kB + bColB, bf[p]);
            #pragma unroll
            for (int mt = 0; mt < 2; ++mt)
                #pragma unroll
                for (int nt = 0; nt < 8; ++nt)
                    mma_bf16(acc[mt][nt], afh[mt], &bf[nt >> 1][(nt & 1) * 2]);
        }

        if (ch < 7) cvtStoreA(((ch + 1) & 1) * ASTG);
    }

    const int g = lane >> 2, t2 = (lane & 3) * 2;
    #pragma unroll
    for (int mt = 0; mt < 2; ++mt) {
        const int r0 = m0 + wm + mt * 16 + g;
        #pragma unroll
        for (int nt = 0; nt < 8; ++nt) {
            const int c = n0 + wn + nt * 8 + t2;
            const float2 bsv = *(const float2*)(bias + c);
            if (HalfOut) {
                __half* C = (__half*)Cv;
                if (r0 < M)
                    *(__half2*)(C + (size_t)r0 * ldc + c) =
                        __floats2half2_rn(acc[mt][nt][0] + bsv.x, acc[mt][nt][1] + bsv.y);
                if (r0 + 8 < M)
                    *(__half2*)(C + (size_t)(r0 + 8) * ldc + c) =
                        __floats2half2_rn(acc[mt][nt][2] + bsv.x, acc[mt][nt][3] + bsv.y);
            } else {
                float* C = (float*)Cv;
                if (r0 < M) {
                    float2 o = { acc[mt][nt][0] + bsv.x, acc[mt][nt][1] + bsv.y };
                    *(float2*)(C + (size_t)r0 * ldc + c) = o;
                }
                if (r0 + 8 < M) {
                    float2 o = { acc[mt][nt][2] + bsv.x, acc[mt][nt][3] + bsv.y };
                    *(float2*)(C + (size_t)(r0 + 8) * ldc + c) = o;
                }
            }
        }
    }
}

// merged value+qc GEMM: grid.y in [0,5): y<2 -> value fp16 (N=256), y>=2 -> qc fp32 (N=384)
__global__ __launch_bounds__(256, 2) void gemm_dual(
    const float* __restrict__ A0, const __nv_bfloat16* __restrict__ B0h,
    const __nv_bfloat16* __restrict__ B0l, const float* __restrict__ bias0,
    __half* __restrict__ C0,
    const float* __restrict__ A1, const __nv_bfloat16* __restrict__ B1h,
    const __nv_bfloat16* __restrict__ B1l, const float* __restrict__ bias1,
    float* __restrict__ C1)
{
    extern __shared__ __align__(16) char smem[];
    const int m0 = blockIdx.x * 128;
    if (blockIdx.y < 2)
        gemm_core<true >(A0, B0h, B0l, bias0, C0, MROWS, 256, m0, blockIdx.y * 128, smem);
    else
        gemm_core<false>(A1, B1h, B1l, bias1, C1, MROWS, 384, m0, (blockIdx.y - 2) * 128, smem);
}

__global__ __launch_bounds__(256, 2) void gemm_single(
    const float* __restrict__ A, const __nv_bfloat16* __restrict__ Bhi,
    const __nv_bfloat16* __restrict__ Blo, const float* __restrict__ bias,
    float* __restrict__ C, int M, int ldc)
{
    extern __shared__ __align__(16) char smem[];
    gemm_core<false>(A, Bhi, Blo, bias, C, M, ldc, blockIdx.x * 128, blockIdx.y * 128, smem);
}

// ---------------- deformable sampling: fp16 value, precomputed corner table ----
__global__ __launch_bounds__(256) void sample_kernel(
    const float* __restrict__ refpts,   // [N*Lq, 4, 2]
    const __half* __restrict__ value,   // [N*S, 256] fp16
    const float* __restrict__ qc,       // [N*Lq, 384]: off(256) | logits(128)
    float* __restrict__ out)            // [N*Lq, 256]
{
    const int q0  = blockIdx.x * 4;
    const int tid = threadIdx.x;

    __shared__ float sh_w[4][8][17];
    __shared__ float sh_x[4][8][17];
    __shared__ float sh_y[4][8][17];
    __shared__ __align__(16) float2 sh_p[4][8][64];

    // softmax weights: 32 runs of 16 logits, 16-lane segments
    #pragma unroll
    for (int i = 0; i < 2; ++i) {
        int run = i * 16 + (tid >> 4);
        int q = run >> 3, h = run & 7, l16 = tid & 15;
        float v = qc[(size_t)(q0 + q) * 384 + 256 + h * 16 + l16];
        float mx = v;
        #pragma unroll
        for (int o = 8; o > 0; o >>= 1) mx = fmaxf(mx, __shfl_xor_sync(0xffffffffu, mx, o));
        float e = __expf(v - mx);
        float s = e;
        #pragma unroll
        for (int o = 8; o > 0; o >>= 1) s += __shfl_xor_sync(0xffffffffu, s, o);
        sh_w[q][h][l16] = e / s;
    }

    // pixel coords: x = ref*W + off - 0.5
    #pragma unroll
    for (int q = 0; q < 4; ++q) {
        int h = tid >> 5, l32 = tid & 31;
        int lvl = l32 >> 3, cc = l32 & 1, s = l32 >> 1;
        float off = qc[(size_t)(q0 + q) * 384 + tid];
        float ref = refpts[((size_t)(q0 + q) * 4 + lvl) * 2 + cc];
        float pix = fmaf(ref, (float)c_WH[lvl], off) - 0.5f;
        if (cc == 0) sh_x[q][h][s] = pix; else sh_y[q][h][s] = pix;
    }
    __syncthreads();

    // 2048 corners, 8 per thread: (q,h,s,c) -> (gw, byteoff)  [512B per position]
    #pragma unroll
    for (int i = 0; i < 8; ++i) {
        const int e = i * 256 + tid;
        const int q = e >> 9, h = (e >> 6) & 7, s = (e >> 2) & 15, c = e & 3;
        const int lvl = s >> 2;
        const int Wl = c_WH[lvl], st = c_ST[lvl];
        const float x = sh_x[q][h][s], y = sh_y[q][h][s], aw = sh_w[q][h][s];
        const float xf = floorf(x), yf = floorf(y);
        const float wx = x - xf, wy = y - yf;
        const int xi = (int)xf + (c & 1);
        const int yi = (int)yf + (c >> 1);
        const float gw = aw * ((c >> 1) ? wy : 1.f - wy) * ((c & 1) ? wx : 1.f - wx);
        const bool valid = (xi >= 0) & (xi < Wl) & (yi >= 0) & (yi < Wl);
        float2 pr;
        pr.x = valid ? gw : 0.f;
        pr.y = __int_as_float(valid ? (st + yi * Wl + xi) * 512 : 0);
        sh_p[q][h][s * 4 + c] = pr;
    }
    __syncthreads();

    // gather: warp = (query, head-half); lane: 4 heads x 8 slots of 4 fp16 channels
    const int w = tid >> 5, lane = tid & 31;
    const int q = w >> 1, half = w & 1;
    const int head = half * 4 + (lane >> 3);
    const int ci = lane & 7;
    const int qg = q0 + q;
    const int n  = (qg >= LQ) ? 1 : 0;

    const char* vb = (const char*)value + ((size_t)n * LQ * 256 + head * 32 + ci * 4) * 2;
    const float4* pp = (const float4*)&sh_p[q][head][0];
    float4 acc = make_float4(0.f, 0.f, 0.f, 0.f);

    #pragma unroll 8
    for (int i = 0; i < 32; ++i) {
        const float4 pw = pp[i];
        const uint2 r0 = __ldg((const uint2*)(vb + (uint32_t)__float_as_int(pw.y)));
        const uint2 r1 = __ldg((const uint2*)(vb + (uint32_t)__float_as_int(pw.w)));
        const float2 a0 = __half22float2(*(const __half2*)&r0.x);
        const float2 a1 = __half22float2(*(const __half2*)&r0.y);
        const float2 b0 = __half22float2(*(const __half2*)&r1.x);
        const float2 b1 = __half22float2(*(const __half2*)&r1.y);
        acc.x = fmaf(pw.x, a0.x, acc.x);
        acc.y = fmaf(pw.x, a0.y, acc.y);
        acc.z = fmaf(pw.x, a1.x, acc.z);
        acc.w = fmaf(pw.x, a1.y, acc.w);
        acc.x = fmaf(pw.z, b0.x, acc.x);
        acc.y = fmaf(pw.z, b0.y, acc.y);
        acc.z = fmaf(pw.z, b1.x, acc.z);
        acc.w = fmaf(pw.z, b1.y, acc.w);
    }
    ((float4*)out)[(size_t)qg * 64 + head * 8 + ci] = acc;
}

// ---------------- launch (single stream) ----------------
extern "C" void kernel_launch(void* const* d_in, const int* in_sizes, int n_in,
                              void* d_out, int out_size)
{
    const float* query  = (const float*)d_in[0];
    const float* refpts = (const float*)d_in[1];
    const float* flat   = (const float*)d_in[2];
    const float* Wv     = (const float*)d_in[5];
    const float* bv     = (const float*)d_in[6];
    const float* Woff   = (const float*)d_in[7];
    const float* boff   = (const float*)d_in[8];
    const float* Wattn  = (const float*)d_in[9];
    const float* battn  = (const float*)d_in[10];
    const float* Wout   = (const float*)d_in[11];
    const float* bout   = (const float*)d_in[12];
    float* out = (float*)d_out;

    __half* gv;
    float *gqc, *gs, *gbqc;
    __nv_bfloat16 *whi, *wlo;
    cudaGetSymbolAddress((void**)&gv,   g_value);
    cudaGetSymbolAddress((void**)&gqc,  g_qc);
    cudaGetSymbolAddress((void**)&gs,   g_samp);
    cudaGetSymbolAddress((void**)&gbqc, g_bqc);
    cudaGetSymbolAddress((void**)&whi,  g_wthi);
    cudaGetSymbolAddress((void**)&wlo,  g_wtlo);

    static bool attr_done = false;
    if (!attr_done) {
        cudaFuncSetAttribute(gemm_dual,   cudaFuncAttributeMaxDynamicSharedMemorySize, GSMEM);
        cudaFuncSetAttribute(gemm_single, cudaFuncAttributeMaxDynamicSharedMemorySize, GSMEM);
        attr_done = true;
    }

    __nv_bfloat16 *wv_h = whi + 0,          *wv_l = wlo + 0;
    __nv_bfloat16 *wq_h = whi + 256 * 256,  *wq_l = wlo + 256 * 256;
    __nv_bfloat16 *wu_h = whi + 640 * 256,  *wu_l = wlo + 640 * 256;

    conv_wt_all<<<896, 256>>>(Wv, Woff, Wattn, Wout, boff, battn, whi, wlo, gbqc);

    const int mblk = MPAD / 128;           // 208
    gemm_dual<<<dim3(mblk, 5), 256, GSMEM>>>(flat, wv_h, wv_l, bv, gv,
                                             query, wq_h, wq_l, gbqc, gqc);
    sample_kernel<<<MROWS / 4, 256>>>(refpts, gv, gqc, gs);
    gemm_single<<<dim3(mblk, 2), 256, GSMEM>>>(gs, wu_h, wu_l, bout, out, MROWS, 256);
}

// round 10
// speedup vs baseline: 1.4229x; 1.1381x over previous
#include <cuda_runtime.h>
#include <cuda_fp16.h>
#include <cstdint>
#include <cstddef>

// ---------------- problem constants ----------------
constexpr int LQ    = 13294;
constexpr int MROWS = 2 * LQ;          // 26588
constexpr int MPAD  = 208 * 128;       // 26624

__constant__ int c_WH[4] = {100, 50, 25, 13};
__constant__ int c_ST[4] = {0, 10000, 12500, 13125};

// ---------------- scratch (device globals) ----------------
__device__ __half g_value[MPAD * 256];            // fp16 value tensor
__device__ float  g_qc   [MPAD * 384];            // [off(256) | logits(128)] per row
__device__ float  g_samp [MPAD * 256];
__device__ float  g_bqc  [384];                   // boff ++ battn
// transposed weights fp16 hi/lo: Wv [0,256), Wqc [256,640), Wout [640,896)
__device__ __half g_wthi[896 * 256];
__device__ __half g_wtlo[896 * 256];

// ---------------- PTX helpers (baseline sm_80+ ISA, legal on compute_103) ----
__device__ __forceinline__ uint32_t smem_u32(const void* p) {
    uint32_t a;
    asm("{ .reg .u64 t; cvta.to.shared.u64 t, %1; cvt.u32.u64 %0, t; }" : "=r"(a) : "l"(p));
    return a;
}
__device__ __forceinline__ void ldsm_x4(uint32_t addr, uint32_t* r) {
    asm volatile("ldmatrix.sync.aligned.m8n8.x4.shared.b16 {%0,%1,%2,%3}, [%4];"
                 : "=r"(r[0]), "=r"(r[1]), "=r"(r[2]), "=r"(r[3]) : "r"(addr));
}
__device__ __forceinline__ void mma_f16(float* c, const uint32_t* a, const uint32_t* b) {
    asm volatile("mma.sync.aligned.m16n8k16.row.col.f32.f16.f16.f32 "
                 "{%0,%1,%2,%3}, {%4,%5,%6,%7}, {%8,%9}, {%0,%1,%2,%3};"
                 : "+f"(c[0]), "+f"(c[1]), "+f"(c[2]), "+f"(c[3])
                 : "r"(a[0]), "r"(a[1]), "r"(a[2]), "r"(a[3]), "r"(b[0]), "r"(b[1]));
}
#define CP_ASYNC16(dst, src) \
    asm volatile("cp.async.cg.shared.global [%0], [%1], 16;" :: "r"(dst), "l"(src) : "memory")
#define CP_COMMIT() asm volatile("cp.async.commit_group;" ::: "memory")
#define CP_WAIT1()  asm volatile("cp.async.wait_group 1;" ::: "memory")

// ---------------- weight conversion (one launch) ----------------
// W[k][n] -> Wt[n][k] fp16 hi/lo (hi = rn(w); lo = rn(w - hi): ~21 mantissa bits)
__global__ __launch_bounds__(256) void conv_wt_all(
    const float* __restrict__ Wv,   const float* __restrict__ Woff,
    const float* __restrict__ Wattn,const float* __restrict__ Wout,
    const float* __restrict__ boff, const float* __restrict__ battn,
    __half* __restrict__ hi, __half* __restrict__ lo,
    float* __restrict__ bqc)
{
    int idx = blockIdx.x * 256 + threadIdx.x;     // 896*256 total
    int ng = idx >> 8, k = idx & 255;
    float a;
    if (ng < 256)       a = Wv  [k * 256 + ng];
    else if (ng < 640) {
        int n = ng - 256;
        a = (n < 256) ? Woff[k * 256 + n] : Wattn[k * 128 + (n - 256)];
    } else              a = Wout[k * 256 + (ng - 640)];
    __half h = __float2half_rn(a);
    hi[idx] = h;
    lo[idx] = __float2half_rn(a - __half2float(h));
    if (idx < 384) bqc[idx] = (idx < 256) ? boff[idx] : battn[idx - 256];
}

// ---------------- fused-convert HMMA GEMM core (fp16, 2 products) ----------
// C[M,N] = A_fp32[M,256] @ Wt^T + bias; C = A16*Whi + A16*Wlo.
// Tile 128x128, BK=32, 256 threads (8 warps, warp tile 32x64).
// A: fp32 LDG -> fp16 smem (2 buffers). B: cp.async 3-stage ring.
constexpr int ASTG  = 10240;                       // A buffer (fp16 hi only)
constexpr int BSTG  = 20480;                       // B stage: BH 10240 + BL 10240
constexpr int OF_BH = 0, OF_BL = 10240;
constexpr int BBASE = 2 * ASTG;                    // 20480
constexpr int GSMEM = BBASE + 3 * BSTG;            // 81920 -> 2 CTAs/SM

template <bool HalfOut>
__device__ __forceinline__ void gemm_core(
    const float* __restrict__ A,
    const __half* __restrict__ Bhi, const __half* __restrict__ Blo,
    const float* __restrict__ bias, void* __restrict__ Cv,
    int M, int ldc, int m0, int n0, char* smem)
{
    const uint32_t sm0 = smem_u32(smem);
    const int tid = threadIdx.x, wid = tid >> 5, lane = tid & 31;
    const int wm = (wid & 3) * 32, wn = (wid >> 2) * 64;

    const int arow = tid >> 1, ak0 = (tid & 1) * 16;
    const bool avalid = (m0 + arow) < M;
    const float* aptr = A + (size_t)(m0 + arow) * 256 + ak0;

    const int br = tid >> 1, bc2 = (tid & 1) * 2;

    const uint32_t aRow = (lane & 15), aColB = (uint32_t)(lane >> 4) * 16;
    const uint32_t bRow = ((uint32_t)(lane >> 4) << 3) + (lane & 7);
    const uint32_t bColB = (uint32_t)((lane >> 3) & 1) * 16;

    float acc[2][8][4] = {};
    float fA[16];

    auto ldgA = [&](int ch) {
        if (avalid) {
            const float* p = aptr + ch * 32;
            #pragma unroll
            for (int j = 0; j < 4; ++j)
                *(float4*)&fA[j * 4] = *(const float4*)(p + j * 4);
        } else {
            #pragma unroll
            for (int j = 0; j < 16; ++j) fA[j] = 0.f;
        }
    };
    auto cvtStoreA = [&](uint32_t off) {
        __half h[16];
        #pragma unroll
        for (int j = 0; j < 16; ++j) h[j] = __float2half_rn(fA[j]);
        const uint32_t o = arow * 80 + ak0 * 2;
        *(uint4*)(smem + off + o)      = ((uint4*)h)[0];
        *(uint4*)(smem + off + o + 16) = ((uint4*)h)[1];
    };
    auto ldB = [&](int ch) {
        const uint32_t sb = sm0 + BBASE + (ch % 3) * BSTG;
        const int k0 = ch * 32;
        #pragma unroll
        for (int i = 0; i < 2; ++i) {
            const int c = bc2 + i;
            const uint32_t dst = sb + br * 80 + c * 16;
            CP_ASYNC16(dst + OF_BH, Bhi + (size_t)(n0 + br) * 256 + k0 + c * 8);
            CP_ASYNC16(dst + OF_BL, Blo + (size_t)(n0 + br) * 256 + k0 + c * 8);
        }
        CP_COMMIT();
    };

    ldB(0); ldB(1);
    ldgA(0);
    cvtStoreA(0);

    for (int ch = 0; ch < 8; ++ch) {
        CP_WAIT1();
        __syncthreads();
        if (ch < 6) ldB(ch + 2); else CP_COMMIT();
        if (ch < 7) ldgA(ch + 1);

        const uint32_t sa = sm0 + (ch & 1) * ASTG;
        const uint32_t sb = sm0 + BBASE + (ch % 3) * BSTG;
        #pragma unroll
        for (int ks = 0; ks < 2; ++ks) {
            const uint32_t kB = ks * 32;
            uint32_t af[2][4], bf[4][4];
            #pragma unroll
            for (int mt = 0; mt < 2; ++mt)
                ldsm_x4(sa + (wm + mt * 16 + aRow) * 80 + kB + aColB, af[mt]);
            #pragma unroll
            for (int p = 0; p < 4; ++p)
                ldsm_x4(sb + OF_BH + (wn + p * 16 + bRow) * 80 + kB + bColB, bf[p]);
            #pragma unroll
            for (int mt = 0; mt < 2; ++mt)
                #pragma unroll
                for (int nt = 0; nt < 8; ++nt)
                    mma_f16(acc[mt][nt], af[mt], &bf[nt >> 1][(nt & 1) * 2]);
            #pragma unroll
            for (int p = 0; p < 4; ++p)
                ldsm_x4(sb + OF_BL + (wn + p * 16 + bRow) * 80 + kB + bColB, bf[p]);
            #pragma unroll
            for (int mt = 0; mt < 2; ++mt)
                #pragma unroll
                for (int nt = 0; nt < 8; ++nt)
                    mma_f16(acc[mt][nt], af[mt], &bf[nt >> 1][(nt & 1) * 2]);
        }

        if (ch < 7) cvtStoreA(((ch + 1) & 1) * ASTG);
    }

    const int g = lane >> 2, t2 = (lane & 3) * 2;
    #pragma unroll
    for (int mt = 0; mt < 2; ++mt) {
        const int r0 = m0 + wm + mt * 16 + g;
        #pragma unroll
        for (int nt = 0; nt < 8; ++nt) {
            const int c = n0 + wn + nt * 8 + t2;
            const float2 bsv = *(const float2*)(bias + c);
            if (HalfOut) {
                __half* C = (__half*)Cv;
                if (r0 < M)
                    *(__half2*)(C + (size_t)r0 * ldc + c) =
                        __floats2half2_rn(acc[mt][nt][0] + bsv.x, acc[mt][nt][1] + bsv.y);
                if (r0 + 8 < M)
                    *(__half2*)(C + (size_t)(r0 + 8) * ldc + c) =
                        __floats2half2_rn(acc[mt][nt][2] + bsv.x, acc[mt][nt][3] + bsv.y);
            } else {
                float* C = (float*)Cv;
                if (r0 < M) {
                    float2 o = { acc[mt][nt][0] + bsv.x, acc[mt][nt][1] + bsv.y };
                    *(float2*)(C + (size_t)r0 * ldc + c) = o;
                }
                if (r0 + 8 < M) {
                    float2 o = { acc[mt][nt][2] + bsv.x, acc[mt][nt][3] + bsv.y };
                    *(float2*)(C + (size_t)(r0 + 8) * ldc + c) = o;
                }
            }
        }
    }
}

// merged value+qc GEMM: grid.y in [0,5): y<2 -> value fp16 (N=256), y>=2 -> qc fp32 (N=384)
__global__ __launch_bounds__(256, 2) void gemm_dual(
    const float* __restrict__ A0, const __half* __restrict__ B0h,
    const __half* __restrict__ B0l, const float* __restrict__ bias0,
    __half* __restrict__ C0,
    const float* __restrict__ A1, const __half* __restrict__ B1h,
    const __half* __restrict__ B1l, const float* __restrict__ bias1,
    float* __restrict__ C1)
{
    extern __shared__ __align__(16) char smem[];
    const int m0 = blockIdx.x * 128;
    if (blockIdx.y < 2)
        gemm_core<true >(A0, B0h, B0l, bias0, C0, MROWS, 256, m0, blockIdx.y * 128, smem);
    else
        gemm_core<false>(A1, B1h, B1l, bias1, C1, MROWS, 384, m0, (blockIdx.y - 2) * 128, smem);
}

__global__ __launch_bounds__(256, 2) void gemm_single(
    const float* __restrict__ A, const __half* __restrict__ Bhi,
    const __half* __restrict__ Blo, const float* __restrict__ bias,
    float* __restrict__ C, int M, int ldc)
{
    extern __shared__ __align__(16) char smem[];
    gemm_core<false>(A, Bhi, Blo, bias, C, M, ldc, blockIdx.x * 128, blockIdx.y * 128, smem);
}

// ---------------- deformable sampling: fp16 value, precomputed corner table ----
__global__ __launch_bounds__(256) void sample_kernel(
    const float* __restrict__ refpts,   // [N*Lq, 4, 2]
    const __half* __restrict__ value,   // [N*S, 256] fp16
    const float* __restrict__ qc,       // [N*Lq, 384]: off(256) | logits(128)
    float* __restrict__ out)            // [N*Lq, 256]
{
    const int q0  = blockIdx.x * 4;
    const int tid = threadIdx.x;

    __shared__ float sh_w[4][8][17];
    __shared__ float sh_x[4][8][17];
    __shared__ float sh_y[4][8][17];
    __shared__ __align__(16) float2 sh_p[4][8][64];

    // softmax weights: 32 runs of 16 logits, 16-lane segments
    #pragma unroll
    for (int i = 0; i < 2; ++i) {
        int run = i * 16 + (tid >> 4);
        int q = run >> 3, h = run & 7, l16 = tid & 15;
        float v = qc[(size_t)(q0 + q) * 384 + 256 + h * 16 + l16];
        float mx = v;
        #pragma unroll
        for (int o = 8; o > 0; o >>= 1) mx = fmaxf(mx, __shfl_xor_sync(0xffffffffu, mx, o));
        float e = __expf(v - mx);
        float s = e;
        #pragma unroll
        for (int o = 8; o > 0; o >>= 1) s += __shfl_xor_sync(0xffffffffu, s, o);
        sh_w[q][h][l16] = e / s;
    }

    // pixel coords: x = ref*W + off - 0.5
    #pragma unroll
    for (int q = 0; q < 4; ++q) {
        int h = tid >> 5, l32 = tid & 31;
        int lvl = l32 >> 3, cc = l32 & 1, s = l32 >> 1;
        float off = qc[(size_t)(q0 + q) * 384 + tid];
        float ref = refpts[((size_t)(q0 + q) * 4 + lvl) * 2 + cc];
        float pix = fmaf(ref, (float)c_WH[lvl], off) - 0.5f;
        if (cc == 0) sh_x[q][h][s] = pix; else sh_y[q][h][s] = pix;
    }
    __syncthreads();

    // 2048 corners, 8 per thread: (q,h,s,c) -> (gw, byteoff)  [512B per position]
    #pragma unroll
    for (int i = 0; i < 8; ++i) {
        const int e = i * 256 + tid;
        const int q = e >> 9, h = (e >> 6) & 7, s = (e >> 2) & 15, c = e & 3;
        const int lvl = s >> 2;
        const int Wl = c_WH[lvl], st = c_ST[lvl];
        const float x = sh_x[q][h][s], y = sh_y[q][h][s], aw = sh_w[q][h][s];
        const float xf = floorf(x), yf = floorf(y);
        const float wx = x - xf, wy = y - yf;
        const int xi = (int)xf + (c & 1);
        const int yi = (int)yf + (c >> 1);
        const float gw = aw * ((c >> 1) ? wy : 1.f - wy) * ((c & 1) ? wx : 1.f - wx);
        const bool valid = (xi >= 0) & (xi < Wl) & (yi >= 0) & (yi < Wl);
        float2 pr;
        pr.x = valid ? gw : 0.f;
        pr.y = __int_as_float(valid ? (st + yi * Wl + xi) * 512 : 0);
        sh_p[q][h][s * 4 + c] = pr;
    }
    __syncthreads();

    // gather: warp = (query, head-half); lane: 4 heads x 8 slots of 4 fp16 channels
    const int w = tid >> 5, lane = tid & 31;
    const int q = w >> 1, half = w & 1;
    const int head = half * 4 + (lane >> 3);
    const int ci = lane & 7;
    const int qg = q0 + q;
    const int n  = (qg >= LQ) ? 1 : 0;

    const char* vb = (const char*)value + ((size_t)n * LQ * 256 + head * 32 + ci * 4) * 2;
    const float4* pp = (const float4*)&sh_p[q][head][0];
    float4 acc = make_float4(0.f, 0.f, 0.f, 0.f);

    #pragma unroll 8
    for (int i = 0; i < 32; ++i) {
        const float4 pw = pp[i];
        const uint2 r0 = __ldg((const uint2*)(vb + (uint32_t)__float_as_int(pw.y)));
        const uint2 r1 = __ldg((const uint2*)(vb + (uint32_t)__float_as_int(pw.w)));
        const float2 a0 = __half22float2(*(const __half2*)&r0.x);
        const float2 a1 = __half22float2(*(const __half2*)&r0.y);
        const float2 b0 = __half22float2(*(const __half2*)&r1.x);
        const float2 b1 = __half22float2(*(const __half2*)&r1.y);
        acc.x = fmaf(pw.x, a0.x, acc.x);
        acc.y = fmaf(pw.x, a0.y, acc.y);
        acc.z = fmaf(pw.x, a1.x, acc.z);
        acc.w = fmaf(pw.x, a1.y, acc.w);
        acc.x = fmaf(pw.z, b0.x, acc.x);
        acc.y = fmaf(pw.z, b0.y, acc.y);
        acc.z = fmaf(pw.z, b1.x, acc.z);
        acc.w = fmaf(pw.z, b1.y, acc.w);
    }
    ((float4*)out)[(size_t)qg * 64 + head * 8 + ci] = acc;
}

// ---------------- launch (single stream) ----------------
extern "C" void kernel_launch(void* const* d_in, const int* in_sizes, int n_in,
                              void* d_out, int out_size)
{
    const float* query  = (const float*)d_in[0];
    const float* refpts = (const float*)d_in[1];
    const float* flat   = (const float*)d_in[2];
    const float* Wv     = (const float*)d_in[5];
    const float* bv     = (const float*)d_in[6];
    const float* Woff   = (const float*)d_in[7];
    const float* boff   = (const float*)d_in[8];
    const float* Wattn  = (const float*)d_in[9];
    const float* battn  = (const float*)d_in[10];
    const float* Wout   = (const float*)d_in[11];
    const float* bout   = (const float*)d_in[12];
    float* out = (float*)d_out;

    __half* gv;
    float *gqc, *gs, *gbqc;
    __half *whi, *wlo;
    cudaGetSymbolAddress((void**)&gv,   g_value);
    cudaGetSymbolAddress((void**)&gqc,  g_qc);
    cudaGetSymbolAddress((void**)&gs,   g_samp);
    cudaGetSymbolAddress((void**)&gbqc, g_bqc);
    cudaGetSymbolAddress((void**)&whi,  g_wthi);
    cudaGetSymbolAddress((void**)&wlo,  g_wtlo);

    static bool attr_done = false;
    if (!attr_done) {
        cudaFuncSetAttribute(gemm_dual,   cudaFuncAttributeMaxDynamicSharedMemorySize, GSMEM);
        cudaFuncSetAttribute(gemm_single, cudaFuncAttributeMaxDynamicSharedMemorySize, GSMEM);
        attr_done = true;
    }

    __half *wv_h = whi + 0,          *wv_l = wlo + 0;
    __half *wq_h = whi + 256 * 256,  *wq_l = wlo + 256 * 256;
    __half *wu_h = whi + 640 * 256,  *wu_l = wlo + 640 * 256;

    conv_wt_all<<<896, 256>>>(Wv, Woff, Wattn, Wout, boff, battn, whi, wlo, gbqc);

    const int mblk = MPAD / 128;           // 208
    gemm_dual<<<dim3(mblk, 5), 256, GSMEM>>>(flat, wv_h, wv_l, bv, gv,
                                             query, wq_h, wq_l, gbqc, gqc);
    sample_kernel<<<MROWS / 4, 256>>>(refpts, gv, gqc, gs);
    gemm_single<<<dim3(mblk, 2), 256, GSMEM>>>(gs, wu_h, wu_l, bout, out, MROWS, 256);
}

// round 11
// speedup vs baseline: 1.6586x; 1.1656x over previous
#include <cuda_runtime.h>
#include <cuda_fp16.h>
#include <cstdint>
#include <cstddef>

// ---------------- problem constants ----------------
constexpr int LQ    = 13294;
constexpr int MROWS = 2 * LQ;          // 26588
constexpr int MPAD  = 208 * 128;       // 26624

__constant__ int c_WH[4] = {100, 50, 25, 13};
__constant__ int c_ST[4] = {0, 10000, 12500, 13125};

// ---------------- scratch (device globals) ----------------
__device__ __half g_value[MPAD * 256];            // fp16 value tensor
__device__ float  g_qc   [MPAD * 384];            // [off(256) | logits(128)] per row
__device__ float  g_samp [MPAD * 256];
__device__ float  g_bqc  [384];                   // boff ++ battn
// transposed fp16 weights: Wv [0,256), Wqc [256,640), Wout [640,896)
__device__ __half g_wt[896 * 256];

// ---------------- PTX helpers (baseline sm_80+ ISA, legal on compute_103) ----
__device__ __forceinline__ uint32_t smem_u32(const void* p) {
    uint32_t a;
    asm("{ .reg .u64 t; cvta.to.shared.u64 t, %1; cvt.u32.u64 %0, t; }" : "=r"(a) : "l"(p));
    return a;
}
__device__ __forceinline__ void ldsm_x4(uint32_t addr, uint32_t* r) {
    asm volatile("ldmatrix.sync.aligned.m8n8.x4.shared.b16 {%0,%1,%2,%3}, [%4];"
                 : "=r"(r[0]), "=r"(r[1]), "=r"(r[2]), "=r"(r[3]) : "r"(addr));
}
__device__ __forceinline__ void mma_f16(float* c, const uint32_t* a, const uint32_t* b) {
    asm volatile("mma.sync.aligned.m16n8k16.row.col.f32.f16.f16.f32 "
                 "{%0,%1,%2,%3}, {%4,%5,%6,%7}, {%8,%9}, {%0,%1,%2,%3};"
                 : "+f"(c[0]), "+f"(c[1]), "+f"(c[2]), "+f"(c[3])
                 : "r"(a[0]), "r"(a[1]), "r"(a[2]), "r"(a[3]), "r"(b[0]), "r"(b[1]));
}
#define CP_ASYNC16(dst, src) \
    asm volatile("cp.async.cg.shared.global [%0], [%1], 16;" :: "r"(dst), "l"(src) : "memory")
#define CP_COMMIT() asm volatile("cp.async.commit_group;" ::: "memory")
#define CP_WAIT1()  asm volatile("cp.async.wait_group 1;" ::: "memory")

// ---------------- weight conversion (one launch) ----------------
// W[k][n] -> Wt[n][k] fp16
__global__ __launch_bounds__(256) void conv_wt_all(
    const float* __restrict__ Wv,   const float* __restrict__ Woff,
    const float* __restrict__ Wattn,const float* __restrict__ Wout,
    const float* __restrict__ boff, const float* __restrict__ battn,
    __half* __restrict__ wt, float* __restrict__ bqc)
{
    int idx = blockIdx.x * 256 + threadIdx.x;     // 896*256 total
    int ng = idx >> 8, k = idx & 255;
    float a;
    if (ng < 256)       a = Wv  [k * 256 + ng];
    else if (ng < 640) {
        int n = ng - 256;
        a = (n < 256) ? Woff[k * 256 + n] : Wattn[k * 128 + (n - 256)];
    } else              a = Wout[k * 256 + (ng - 640)];
    wt[idx] = __float2half_rn(a);
    if (idx < 384) bqc[idx] = (idx < 256) ? boff[idx] : battn[idx - 256];
}

// ---------------- fused-convert HMMA GEMM core (fp16, single product) -------
// C[M,N] = A16[M,256] @ Wt^T + bias.
// Tile 128x128, BK=32, 256 threads (8 warps, warp tile 32x64).
// A: fp32 LDG -> fp16 smem (2 buffers). B: cp.async 3-stage ring.
constexpr int ASTG  = 10240;                       // A buffer (fp16)
constexpr int BSTG  = 10240;                       // B stage (fp16)
constexpr int BBASE = 2 * ASTG;                    // 20480
constexpr int GSMEM = BBASE + 3 * BSTG;            // 51200 -> 2 CTAs/SM

template <bool HalfOut>
__device__ __forceinline__ void gemm_core(
    const float* __restrict__ A,
    const __half* __restrict__ B,
    const float* __restrict__ bias, void* __restrict__ Cv,
    int M, int ldc, int m0, int n0, char* smem)
{
    const uint32_t sm0 = smem_u32(smem);
    const int tid = threadIdx.x, wid = tid >> 5, lane = tid & 31;
    const int wm = (wid & 3) * 32, wn = (wid >> 2) * 64;

    const int arow = tid >> 1, ak0 = (tid & 1) * 16;
    const bool avalid = (m0 + arow) < M;
    const float* aptr = A + (size_t)(m0 + arow) * 256 + ak0;

    const int br = tid >> 1, bc = tid & 1;         // 512 x 16B chunks: row=tid>>1, chunk=tid&1..+?
    // B tile: 128 rows x 32 cols fp16 = 128 x 64B = 2 chunks of 16B x2 per row pair
    // 256 threads x 2 half-rows: each thread does one 16B chunk of rows (tid>>1), chunks (tid&1)*? 
    // rows 128, 4 x 16B per row = 512 chunks; threads 256 -> 2 chunks each

    const uint32_t aRow = (lane & 15), aColB = (uint32_t)(lane >> 4) * 16;
    const uint32_t bRow = ((uint32_t)(lane >> 4) << 3) + (lane & 7);
    const uint32_t bColB = (uint32_t)((lane >> 3) & 1) * 16;

    float acc[2][8][4] = {};
    float fA[16];

    auto ldgA = [&](int ch) {
        if (avalid) {
            const float* p = aptr + ch * 32;
            #pragma unroll
            for (int j = 0; j < 4; ++j)
                *(float4*)&fA[j * 4] = *(const float4*)(p + j * 4);
        } else {
            #pragma unroll
            for (int j = 0; j < 16; ++j) fA[j] = 0.f;
        }
    };
    auto cvtStoreA = [&](uint32_t off) {
        __half h[16];
        #pragma unroll
        for (int j = 0; j < 16; ++j) h[j] = __float2half_rn(fA[j]);
        const uint32_t o = arow * 80 + ak0 * 2;
        *(uint4*)(smem + off + o)      = ((uint4*)h)[0];
        *(uint4*)(smem + off + o + 16) = ((uint4*)h)[1];
    };
    auto ldB = [&](int ch) {
        const uint32_t sb = sm0 + BBASE + (ch % 3) * BSTG;
        const int k0 = ch * 32;
        #pragma unroll
        for (int i = 0; i < 2; ++i) {
            const int c = bc * 2 + i;
            CP_ASYNC16(sb + br * 80 + c * 16, B + (size_t)(n0 + br) * 256 + k0 + c * 8);
        }
        CP_COMMIT();
    };

    ldB(0); ldB(1);
    ldgA(0);
    cvtStoreA(0);

    for (int ch = 0; ch < 8; ++ch) {
        CP_WAIT1();
        __syncthreads();
        if (ch < 6) ldB(ch + 2); else CP_COMMIT();
        if (ch < 7) ldgA(ch + 1);

        const uint32_t sa = sm0 + (ch & 1) * ASTG;
        const uint32_t sb = sm0 + BBASE + (ch % 3) * BSTG;
        #pragma unroll
        for (int ks = 0; ks < 2; ++ks) {
            const uint32_t kB = ks * 32;
            uint32_t af[2][4], bf[4][4];
            #pragma unroll
            for (int mt = 0; mt < 2; ++mt)
                ldsm_x4(sa + (wm + mt * 16 + aRow) * 80 + kB + aColB, af[mt]);
            #pragma unroll
            for (int p = 0; p < 4; ++p)
                ldsm_x4(sb + (wn + p * 16 + bRow) * 80 + kB + bColB, bf[p]);
            #pragma unroll
            for (int mt = 0; mt < 2; ++mt)
                #pragma unroll
                for (int nt = 0; nt < 8; ++nt)
                    mma_f16(acc[mt][nt], af[mt], &bf[nt >> 1][(nt & 1) * 2]);
        }

        if (ch < 7) cvtStoreA(((ch + 1) & 1) * ASTG);
    }

    const int g = lane >> 2, t2 = (lane & 3) * 2;
    #pragma unroll
    for (int mt = 0; mt < 2; ++mt) {
        const int r0 = m0 + wm + mt * 16 + g;
        #pragma unroll
        for (int nt = 0; nt < 8; ++nt) {
            const int c = n0 + wn + nt * 8 + t2;
            const float2 bsv = *(const float2*)(bias + c);
            if (HalfOut) {
                __half* C = (__half*)Cv;
                if (r0 < M)
                    *(__half2*)(C + (size_t)r0 * ldc + c) =
                        __floats2half2_rn(acc[mt][nt][0] + bsv.x, acc[mt][nt][1] + bsv.y);
                if (r0 + 8 < M)
                    *(__half2*)(C + (size_t)(r0 + 8) * ldc + c) =
                        __floats2half2_rn(acc[mt][nt][2] + bsv.x, acc[mt][nt][3] + bsv.y);
            } else {
                float* C = (float*)Cv;
                if (r0 < M) {
                    float2 o = { acc[mt][nt][0] + bsv.x, acc[mt][nt][1] + bsv.y };
                    *(float2*)(C + (size_t)r0 * ldc + c) = o;
                }
                if (r0 + 8 < M) {
                    float2 o = { acc[mt][nt][2] + bsv.x, acc[mt][nt][3] + bsv.y };
                    *(float2*)(C + (size_t)(r0 + 8) * ldc + c) = o;
                }
            }
        }
    }
}

// merged value+qc GEMM: grid.y in [0,5): y<2 -> value fp16 (N=256), y>=2 -> qc fp32 (N=384)
__global__ __launch_bounds__(256, 2) void gemm_dual(
    const float* __restrict__ A0, const __half* __restrict__ B0,
    const float* __restrict__ bias0, __half* __restrict__ C0,
    const float* __restrict__ A1, const __half* __restrict__ B1,
    const float* __restrict__ bias1, float* __restrict__ C1)
{
    extern __shared__ __align__(16) char smem[];
    const int m0 = blockIdx.x * 128;
    if (blockIdx.y < 2)
        gemm_core<true >(A0, B0, bias0, C0, MROWS, 256, m0, blockIdx.y * 128, smem);
    else
        gemm_core<false>(A1, B1, bias1, C1, MROWS, 384, m0, (blockIdx.y - 2) * 128, smem);
}

__global__ __launch_bounds__(256, 2) void gemm_single(
    const float* __restrict__ A, const __half* __restrict__ B,
    const float* __restrict__ bias, float* __restrict__ C, int M, int ldc)
{
    extern __shared__ __align__(16) char smem[];
    gemm_core<false>(A, B, bias, C, M, ldc, blockIdx.x * 128, blockIdx.y * 128, smem);
}

// ---------------- deformable sampling: fp16 value, precomputed corner table ----
__global__ __launch_bounds__(256) void sample_kernel(
    const float* __restrict__ refpts,   // [N*Lq, 4, 2]
    const __half* __restrict__ value,   // [N*S, 256] fp16
    const float* __restrict__ qc,       // [N*Lq, 384]: off(256) | logits(128)
    float* __restrict__ out)            // [N*Lq, 256]
{
    const int q0  = blockIdx.x * 4;
    const int tid = threadIdx.x;

    __shared__ float sh_w[4][8][17];
    __shared__ float sh_x[4][8][17];
    __shared__ float sh_y[4][8][17];
    __shared__ __align__(16) float2 sh_p[4][8][64];

    // softmax weights: 32 runs of 16 logits, 16-lane segments
    #pragma unroll
    for (int i = 0; i < 2; ++i) {
        int run = i * 16 + (tid >> 4);
        int q = run >> 3, h = run & 7, l16 = tid & 15;
        float v = qc[(size_t)(q0 + q) * 384 + 256 + h * 16 + l16];
        float mx = v;
        #pragma unroll
        for (int o = 8; o > 0; o >>= 1) mx = fmaxf(mx, __shfl_xor_sync(0xffffffffu, mx, o));
        float e = __expf(v - mx);
        float s = e;
        #pragma unroll
        for (int o = 8; o > 0; o >>= 1) s += __shfl_xor_sync(0xffffffffu, s, o);
        sh_w[q][h][l16] = e / s;
    }

    // pixel coords: x = ref*W + off - 0.5
    #pragma unroll
    for (int q = 0; q < 4; ++q) {
        int h = tid >> 5, l32 = tid & 31;
        int lvl = l32 >> 3, cc = l32 & 1, s = l32 >> 1;
        float off = qc[(size_t)(q0 + q) * 384 + tid];
        float ref = refpts[((size_t)(q0 + q) * 4 + lvl) * 2 + cc];
        float pix = fmaf(ref, (float)c_WH[lvl], off) - 0.5f;
        if (cc == 0) sh_x[q][h][s] = pix; else sh_y[q][h][s] = pix;
    }
    __syncthreads();

    // 2048 corners, 8 per thread: (q,h,s,c) -> (gw, byteoff)  [512B per position]
    #pragma unroll
    for (int i = 0; i < 8; ++i) {
        const int e = i * 256 + tid;
        const int q = e >> 9, h = (e >> 6) & 7, s = (e >> 2) & 15, c = e & 3;
        const int lvl = s >> 2;
        const int Wl = c_WH[lvl], st = c_ST[lvl];
        const float x = sh_x[q][h][s], y = sh_y[q][h][s], aw = sh_w[q][h][s];
        const float xf = floorf(x), yf = floorf(y);
        const float wx = x - xf, wy = y - yf;
        const int xi = (int)xf + (c & 1);
        const int yi = (int)yf + (c >> 1);
        const float gw = aw * ((c >> 1) ? wy : 1.f - wy) * ((c & 1) ? wx : 1.f - wx);
        const bool valid = (xi >= 0) & (xi < Wl) & (yi >= 0) & (yi < Wl);
        float2 pr;
        pr.x = valid ? gw : 0.f;
        pr.y = __int_as_float(valid ? (st + yi * Wl + xi) * 512 : 0);
        sh_p[q][h][s * 4 + c] = pr;
    }
    __syncthreads();

    // gather: warp = (query, head-half); lane: 4 heads x 8 slots of 4 fp16 channels
    const int w = tid >> 5, lane = tid & 31;
    const int q = w >> 1, half = w & 1;
    const int head = half * 4 + (lane >> 3);
    const int ci = lane & 7;
    const int qg = q0 + q;
    const int n  = (qg >= LQ) ? 1 : 0;

    const char* vb = (const char*)value + ((size_t)n * LQ * 256 + head * 32 + ci * 4) * 2;
    const float4* pp = (const float4*)&sh_p[q][head][0];
    float4 acc = make_float4(0.f, 0.f, 0.f, 0.f);

    #pragma unroll 8
    for (int i = 0; i < 32; ++i) {
        const float4 pw = pp[i];
        const uint2 r0 = __ldg((const uint2*)(vb + (uint32_t)__float_as_int(pw.y)));
        const uint2 r1 = __ldg((const uint2*)(vb + (uint32_t)__float_as_int(pw.w)));
        const float2 a0 = __half22float2(*(const __half2*)&r0.x);
        const float2 a1 = __half22float2(*(const __half2*)&r0.y);
        const float2 b0 = __half22float2(*(const __half2*)&r1.x);
        const float2 b1 = __half22float2(*(const __half2*)&r1.y);
        acc.x = fmaf(pw.x, a0.x, acc.x);
        acc.y = fmaf(pw.x, a0.y, acc.y);
        acc.z = fmaf(pw.x, a1.x, acc.z);
        acc.w = fmaf(pw.x, a1.y, acc.w);
        acc.x = fmaf(pw.z, b0.x, acc.x);
        acc.y = fmaf(pw.z, b0.y, acc.y);
        acc.z = fmaf(pw.z, b1.x, acc.z);
        acc.w = fmaf(pw.z, b1.y, acc.w);
    }
    ((float4*)out)[(size_t)qg * 64 + head * 8 + ci] = acc;
}

// ---------------- launch (single stream) ----------------
extern "C" void kernel_launch(void* const* d_in, const int* in_sizes, int n_in,
                              void* d_out, int out_size)
{
    const float* query  = (const float*)d_in[0];
    const float* refpts = (const float*)d_in[1];
    const float* flat   = (const float*)d_in[2];
    const float* Wv     = (const float*)d_in[5];
    const float* bv     = (const float*)d_in[6];
    const float* Woff   = (const float*)d_in[7];
    const float* boff   = (const float*)d_in[8];
    const float* Wattn  = (const float*)d_in[9];
    const float* battn  = (const float*)d_in[10];
    const float* Wout   = (const float*)d_in[11];
    const float* bout   = (const float*)d_in[12];
    float* out = (float*)d_out;

    __half* gv;
    float *gqc, *gs, *gbqc;
    __half *wt;
    cudaGetSymbolAddress((void**)&gv,   g_value);
    cudaGetSymbolAddress((void**)&gqc,  g_qc);
    cudaGetSymbolAddress((void**)&gs,   g_samp);
    cudaGetSymbolAddress((void**)&gbqc, g_bqc);
    cudaGetSymbolAddress((void**)&wt,   g_wt);

    static bool attr_done = false;
    if (!attr_done) {
        cudaFuncSetAttribute(gemm_dual,   cudaFuncAttributeMaxDynamicSharedMemorySize, GSMEM);
        cudaFuncSetAttribute(gemm_single, cudaFuncAttributeMaxDynamicSharedMemorySize, GSMEM);
        attr_done = true;
    }

    __half *wv = wt + 0, *wq = wt + 256 * 256, *wu = wt + 640 * 256;

    conv_wt_all<<<896, 256>>>(Wv, Woff, Wattn, Wout, boff, battn, wt, gbqc);

    const int mblk = MPAD / 128;           // 208
    gemm_dual<<<dim3(mblk, 5), 256, GSMEM>>>(flat, wv, bv, gv,
                                             query, wq, gbqc, gqc);
    sample_kernel<<<MROWS / 4, 256>>>(refpts, gv, gqc, gs);
    gemm_single<<<dim3(mblk, 2), 256, GSMEM>>>(gs, wu, bout, out, MROWS, 256);
}